// round 12
// baseline (speedup 1.0000x reference)
#include <cuda_runtime.h>

#define BB 2
#define KK 33
#define NN 50000
#define EE 800000
#define RR 200
#define DD 64
#define LL 3
#define NROWS (BB*NN)          /* 100000 */
#define NWORDS (NROWS/32)      /* 3125, exact */
#define TABW (NN*2/32)         /* 3125 */
#define GRID 148
#define BLK 512
#define NTHREADS (GRID*BLK)    /* 75776 */
#define NWARPS (NTHREADS/32)   /* 2368 */
#define WPB ((NWORDS + GRID - 1)/GRID)   /* 22 mask words per block */
#define SC_ITERS 3             /* ceil((EE/4)/NTHREADS) */
#define ROWF 0x100000          /* worklist delta flag (row < 2^17) */

__device__ __align__(16) float g_x[NROWS*DD];
__device__ __align__(16) float g_agg[NROWS*DD];   // invariant: zero at phase entry
__device__ unsigned g_xmask[NWORDS];
__device__ unsigned g_amask[NWORDS];              // invariant: zero at phase entry
__device__ unsigned g_tab[TABW];                  // 2 bits/node, mirrors xmask
__device__ float g_query[BB*DD];
__device__ int   g_h0[BB];
__device__ float g_zv[LL][DD];
__device__ int   g_zfl[LL];
__device__ int   g_b64;

// Tree grid barrier: per-block arrival slots + single release word.
// Generations are ABSOLUTE and monotone across launches/replays.
__device__ unsigned g_arrive[GRID];
__device__ volatile unsigned g_rel;

__device__ __forceinline__ void gridbar(unsigned target) {
    __syncthreads();
    if (blockIdx.x == 0) {
        int t = threadIdx.x;
        if (t > 0 && t < GRID) {
            volatile unsigned* a = (volatile unsigned*)&g_arrive[t];
            while (*a < target) __nanosleep(32);
        }
        __syncthreads();
        if (t == 0) { __threadfence(); g_rel = target; }
    } else {
        if (threadIdx.x == 0) {
            __threadfence();   // publish block's writes
            ((volatile unsigned*)g_arrive)[blockIdx.x] = target;
            while (g_rel < target) __nanosleep(32);
        }
    }
    __syncthreads();
}

__device__ __forceinline__ int clampi(int v, int hi) {
    return v < 0 ? 0 : (v >= hi ? hi - 1 : v);
}
// bit-interleave: bit i of x -> bit 2i
__device__ __forceinline__ unsigned ileave16(unsigned x) {
    x = (x | (x << 8)) & 0x00FF00FFu;
    x = (x | (x << 4)) & 0x0F0F0F0Fu;
    x = (x | (x << 2)) & 0x33333333u;
    x = (x | (x << 1)) & 0x55555555u;
    return x;
}

__global__ void __launch_bounds__(BLK, 1)
k_main(const float* __restrict__ rel,
       const float* __restrict__ layer_w,
       const float* __restrict__ layer_b,
       const float* __restrict__ ln_g,
       const float* __restrict__ ln_b,
       const float* __restrict__ w1,
       const float* __restrict__ b1,
       const float* __restrict__ w2,
       const float* __restrict__ b2,
       const void*  __restrict__ batch,
       const int*   __restrict__ edge_index,
       const int*   __restrict__ etype,
       float*       __restrict__ out)
{
    __shared__ float s_W[2*DD*DD];    // 32KB: current layer's weights
    __shared__ int   s_wl[WPB*32];    // block-local row worklist (<=704)
    __shared__ int   s_cnt;
    __shared__ float s_sb[LL][DD];
    __shared__ float s_mv[LL][2];
    __shared__ float s_feat[2*DD];
    __shared__ float s_hs[DD];
    __shared__ unsigned s_base;

    const int tid   = threadIdx.x;
    const int gid   = blockIdx.x * BLK + tid;
    const int lane  = tid & 31;
    const int bwarp = tid >> 5;                       // warp in block (0..15)
    const int gwarp = gid >> 5;

    if (tid == 0) s_base = g_rel;     // barrier generation base for this launch
    __syncthreads();

    // ---------------- P0: sparse clean + distributed setup -----------------
    for (int w = gwarp; w < NWORDS; w += NWARPS) {
        unsigned m = g_xmask[w];
        if (m) {
            unsigned mm = m;
            while (mm) {
                int j = __ffs(mm) - 1; mm &= mm - 1;
                int row = w * 32 + j;
                ((float2*)g_x)[(size_t)row*32 + lane] = make_float2(0.f, 0.f);
            }
            if (lane == 0) g_xmask[w] = 0u;
        }
        if (lane == 0) g_tab[w] = 0u;
    }
    // Distributed setup: owner warps seed boundary/query/masks.
    {
        const int* bw = (const int*)batch;
        const long long* bl64 = (const long long*)batch;
        int bad = 0;
        for (int i = lane; i < 99; i += 32)           // odd words 1..197
            if (bw[2*i + 1] != 0) bad = 1;
        int is64 = (__ballot_sync(0xffffffffu, bad) == 0);
        if (gwarp == 0 && lane == 0) g_b64 = is64;
        #pragma unroll
        for (int b = 0; b < BB; b++) {
            int i0 = (b*KK)*3;
            int h0 = clampi(is64 ? (int)bl64[i0    ] : bw[i0    ], NN);
            int r0 = clampi(is64 ? (int)bl64[i0 + 2] : bw[i0 + 2], RR);
            int row = b*NN + h0;
            int wx = row >> 5;
            if (wx % NWARPS == gwarp) {               // xmask/x/query owner
                float2 q = ((const float2*)rel)[((size_t)b*RR + r0)*32 + lane];
                ((float2*)g_x)[(size_t)row*32 + lane] = q;
                ((float2*)g_query)[b*32 + lane] = q;
                if (lane == 0) {
                    g_h0[b] = h0;
                    g_xmask[wx] |= 1u << (row & 31);  // exclusive owner
                }
            }
            int wt = h0 >> 4;
            if (wt % NWARPS == gwarp && lane == 0)    // tab owner
                atomicOr(&g_tab[wt], 1u << (((h0 & 15) << 1) + b));
        }
    }
    // z_l = relu(LN(layer_b[l])) — block 0
    if (blockIdx.x == 0 && tid < LL) g_zfl[tid] = 0;
    if (blockIdx.x == 0 && tid < LL*DD)
        s_sb[tid >> 6][tid & 63] = layer_b[tid];
    __syncthreads();
    if (blockIdx.x == 0 && tid < LL) {
        float su = 0.f, sq = 0.f;
        for (int i = 0; i < DD; i++) { float v = s_sb[tid][i]; su += v; sq += v*v; }
        float mu = su * (1.f/DD);
        s_mv[tid][0] = mu;
        s_mv[tid][1] = sq * (1.f/DD) - mu*mu;
    }
    __syncthreads();
    if (blockIdx.x == 0 && tid < LL*DD) {
        int l = tid >> 6, d = tid & 63;
        float v = s_sb[l][d];
        float z = (v - s_mv[l][0]) * rsqrtf(s_mv[l][1] + 1e-5f) * ln_g[tid] + ln_b[tid];
        z = fmaxf(z, 0.f);
        g_zv[l][d] = z;
        if (z != 0.f) atomicOr(&g_zfl[l], 1);
    }
    gridbar(s_base + 1);

    // ---------------- layers ----------------------------------------------
    for (int l = 0; l < LL; l++) {
        // stage this layer's weights into smem (overlaps with scatter)
        {
            const float4* Wsrc = (const float4*)(layer_w + (size_t)l*2*DD*DD);
            float4* Wdst = (float4*)s_W;
            for (int i = tid; i < 2*DD*DD/4; i += BLK) Wdst[i] = Wsrc[i];
            if (tid == 0) s_cnt = 0;
        }
        // ---- scatter: agg[b,dst] += x[b,src] * rel[b,etype] --------------
        {
            int4 s4v[SC_ITERS];
            unsigned pk[SC_ITERS];
            #pragma unroll
            for (int it = 0; it < SC_ITERS; it++) {
                int idx = gid + it * NTHREADS;
                s4v[it] = (idx*4 < EE) ? ((const int4*)edge_index)[idx]
                                       : make_int4(0, 0, 0, 0);
            }
            #pragma unroll
            for (int it = 0; it < SC_ITERS; it++) {
                int idx = gid + it * NTHREADS;
                unsigned p = 0;
                if (idx*4 < EE) {
                    p  = ((g_tab[s4v[it].x >> 4] >> ((s4v[it].x & 15) << 1)) & 3u);
                    p |= ((g_tab[s4v[it].y >> 4] >> ((s4v[it].y & 15) << 1)) & 3u) << 2;
                    p |= ((g_tab[s4v[it].z >> 4] >> ((s4v[it].z & 15) << 1)) & 3u) << 4;
                    p |= ((g_tab[s4v[it].w >> 4] >> ((s4v[it].w & 15) << 1)) & 3u) << 6;
                }
                pk[it] = p;
            }
            #pragma unroll
            for (int it = 0; it < SC_ITERS; it++) {
                if (__ballot_sync(0xffffffffu, pk[it] != 0) == 0) continue;
                int base = (gid + it * NTHREADS) * 4;
                int srcs[4] = {s4v[it].x, s4v[it].y, s4v[it].z, s4v[it].w};
                #pragma unroll
                for (int k = 0; k < 4; k++) {
                    unsigned prk = (pk[it] >> (2*k)) & 3u;
                    unsigned b0 = __ballot_sync(0xffffffffu, prk & 1u);
                    unsigned b1 = __ballot_sync(0xffffffffu, prk & 2u);
                    unsigned act = b0 | b1;
                    while (act) {
                        int j = __ffs(act) - 1;
                        act &= act - 1;
                        int ej = __shfl_sync(0xffffffffu, base, j) + k;
                        int sj = __shfl_sync(0xffffffffu, srcs[k], j);
                        int dj = 0, tj = 0;
                        if (lane == j) { dj = edge_index[EE + ej]; tj = etype[ej]; }
                        dj = __shfl_sync(0xffffffffu, dj, j);
                        tj = __shfl_sync(0xffffffffu, tj, j);
                        #pragma unroll
                        for (int b = 0; b < BB; b++) {
                            unsigned bb = b ? b1 : b0;
                            if (!((bb >> j) & 1)) continue;   // uniform
                            float2 xv = ((const float2*)g_x)[((size_t)(b*NN + sj))*32 + lane];
                            float2 rv = ((const float2*)rel)[((size_t)(b*RR + tj))*32 + lane];
                            float* ap = &g_agg[((size_t)(b*NN + dj))*DD + 2*lane];
                            atomicAdd(ap,     xv.x * rv.x);
                            atomicAdd(ap + 1, xv.y * rv.y);
                            if (lane == 0) {
                                int row = b*NN + dj;
                                atomicOr(&g_amask[row >> 5], 1u << (row & 31));
                            }
                        }
                    }
                }
            }
        }
        gridbar(s_base + 2 + 2*l);

        // ---- fused compact + update over this block's 22 mask words ------
        // Worklist entries carry a delta flag (bit 20): row newly activated
        // this layer => x row is still all-zero.
        if (tid < WPB) {
            int w = blockIdx.x * WPB + tid;
            if (w < NWORDS) {
                unsigned xm = g_xmask[w];
                unsigned am = g_amask[w];
                unsigned act = xm | am;
                unsigned delta = am & ~xm;
                if (am) {
                    g_amask[w] = 0u;
                    if (delta) {
                        g_xmask[w] = act;
                        #pragma unroll
                        for (int h = 0; h < 2; h++) {       // 16-row halves
                            unsigned bits = (delta >> (16*h)) & 0xFFFFu;
                            if (!bits) continue;
                            int rowbase = w * 32 + 16*h;    // multiple of 16
                            if (rowbase < NN)
                                atomicOr(&g_tab[rowbase >> 4], ileave16(bits));
                            else {
                                int node = rowbase - NN;    // NN%16==0
                                atomicOr(&g_tab[node >> 4], ileave16(bits) << 1);
                            }
                        }
                    }
                }
                if (act) {
                    int n = __popc(act);
                    int base = atomicAdd(&s_cnt, n);
                    unsigned mm = act;
                    while (mm) {
                        int j = __ffs(mm) - 1; mm &= mm - 1;
                        s_wl[base++] = (w * 32 + j) | (((delta >> j) & 1u) ? ROWF : 0);
                    }
                }
            }
        }
        __syncthreads();

        // ---- update: 4 worklist rows per warp pass (shared W loads) ------
        {
            int cnt = s_cnt;
            float bj0  = layer_b[l*DD + 2*lane], bj1  = layer_b[l*DD + 2*lane + 1];
            float gj0  = ln_g[l*DD + 2*lane],    gj1  = ln_g[l*DD + 2*lane + 1];
            float btj0 = ln_b[l*DD + 2*lane],    btj1 = ln_b[l*DD + 2*lane + 1];
            for (int i0 = bwarp*4; i0 < cnt; i0 += (BLK/32)*4) {
                int rowv[4], dv[4];
                float2 a2[4], x2[4];
                float acc0[4], acc1[4];
                #pragma unroll
                for (int r = 0; r < 4; r++) {
                    if (i0 + r < cnt) {
                        int e = s_wl[i0 + r];          // broadcast LDS
                        rowv[r] = e & (ROWF - 1);
                        dv[r]   = (e & ROWF) ? 1 : 0;
                    } else { rowv[r] = -1; dv[r] = 1; }
                }
                #pragma unroll
                for (int r = 0; r < 4; r++) {
                    a2[r] = make_float2(0.f, 0.f);
                    x2[r] = make_float2(0.f, 0.f);
                    if (rowv[r] >= 0) {
                        int row = rowv[r];
                        int b   = row / NN;
                        int n   = row - b * NN;
                        a2[r] = ((float2*)g_agg)[(size_t)row*32 + lane];
                        if (!dv[r]) x2[r] = ((float2*)g_x)[(size_t)row*32 + lane];
                        if (n == g_h0[b]) {
                            a2[r].x += g_query[b*DD + 2*lane];
                            a2[r].y += g_query[b*DD + 2*lane + 1];
                        }
                    }
                    acc0[r] = bj0; acc1[r] = bj1;
                }
                int anyx = dv[0] & dv[1] & dv[2] & dv[3];  // 1 => all delta
                #pragma unroll 4
                for (int ii = 0; ii < 32; ii++) {          // cat[0:64] = agg
                    float2 w0 = ((const float2*)(s_W + (2*ii    )*DD))[lane];
                    float2 w1v = ((const float2*)(s_W + (2*ii + 1)*DD))[lane];
                    #pragma unroll
                    for (int r = 0; r < 4; r++) {
                        if (rowv[r] < 0) continue;         // uniform
                        float cx = __shfl_sync(0xffffffffu, a2[r].x, ii);
                        float cy = __shfl_sync(0xffffffffu, a2[r].y, ii);
                        acc0[r] += cx*w0.x + cy*w1v.x;
                        acc1[r] += cx*w0.y + cy*w1v.y;
                    }
                }
                if (!anyx) {
                    #pragma unroll 4
                    for (int ii = 0; ii < 32; ii++) {      // cat[64:128] = x
                        float2 w0 = ((const float2*)(s_W + (64 + 2*ii    )*DD))[lane];
                        float2 w1v = ((const float2*)(s_W + (64 + 2*ii + 1)*DD))[lane];
                        #pragma unroll
                        for (int r = 0; r < 4; r++) {
                            if (rowv[r] < 0 || dv[r]) continue;   // uniform
                            float cx = __shfl_sync(0xffffffffu, x2[r].x, ii);
                            float cy = __shfl_sync(0xffffffffu, x2[r].y, ii);
                            acc0[r] += cx*w0.x + cy*w1v.x;
                            acc1[r] += cx*w0.y + cy*w1v.y;
                        }
                    }
                }
                #pragma unroll
                for (int r = 0; r < 4; r++) {
                    if (rowv[r] < 0) continue;
                    int row = rowv[r];
                    float su = acc0[r] + acc1[r];
                    float sq = acc0[r]*acc0[r] + acc1[r]*acc1[r];
                    #pragma unroll
                    for (int o = 16; o; o >>= 1) {
                        su += __shfl_xor_sync(0xffffffffu, su, o);
                        sq += __shfl_xor_sync(0xffffffffu, sq, o);
                    }
                    float mu  = su * (1.f/DD);
                    float var = sq * (1.f/DD) - mu*mu;
                    float rs  = rsqrtf(var + 1e-5f);
                    float u0 = fmaxf((acc0[r] - mu)*rs*gj0 + btj0, 0.f);
                    float u1 = fmaxf((acc1[r] - mu)*rs*gj1 + btj1, 0.f);
                    x2[r].x += u0; x2[r].y += u1;
                    ((float2*)g_x)[(size_t)row*32 + lane] = x2[r];
                    ((float2*)g_agg)[(size_t)row*32 + lane] = make_float2(0.f, 0.f);
                }
            }
            // cold path: dense z_l densify (z_l == 0 for these inputs)
            if (l < LL - 1 && g_zfl[l]) {
                for (int r = gid; r < NROWS; r += NTHREADS) {
                    if (!((g_xmask[r >> 5] >> (r & 31)) & 1)) {
                        for (int d = 0; d < DD; d++)
                            g_x[(size_t)r*DD + d] += g_zv[l][d];
                        atomicOr(&g_xmask[r >> 5], 1u << (r & 31));
                    }
                }
                for (int r = gid; r < TABW; r += NTHREADS)
                    g_tab[r] = 0xFFFFFFFFu;
            }
        }
        gridbar(s_base + 3 + 2*l);
    }

    // ---------------- score ------------------------------------------------
    if (blockIdx.x < BB*KK) {
        int b = blockIdx.x / KK, k = blockIdx.x % KK;
        if (tid < DD) {
            int ti = (b*KK + k)*3 + 1;
            int t  = clampi(g_b64 ? (int)((const long long*)batch)[ti]
                                  : ((const int*)batch)[ti], NN);
            int row = b*NN + t;
            float f = g_x[(size_t)row*DD + tid];
            if (g_zfl[LL-1] && !((g_xmask[row >> 5] >> (row & 31)) & 1))
                f += g_zv[LL-1][tid];
            s_feat[tid]      = f;
            s_feat[DD + tid] = g_query[b*DD + tid];
        }
        __syncthreads();
        if (tid < DD) {
            float acc = b1[tid];
            #pragma unroll 8
            for (int i = 0; i < 2*DD; i++) acc += s_feat[i] * w1[i*DD + tid];
            float h = fmaxf(acc, 0.f);
            s_hs[tid] = h * w2[tid];
        }
        __syncthreads();
        if (tid == 0) {
            float s = b2[0];
            for (int i = 0; i < DD; i++) s += s_hs[i];
            out[b*KK + k] = s;
        }
    }
}

// ---------------------------------------------------------------------------
extern "C" void kernel_launch(void* const* d_in, const int* in_sizes, int n_in,
                              void* d_out, int out_size) {
    const float* rel      = (const float*)d_in[0];
    const float* layer_w  = (const float*)d_in[1];
    const float* layer_b  = (const float*)d_in[2];
    const float* ln_g     = (const float*)d_in[3];
    const float* ln_b     = (const float*)d_in[4];
    const float* mlp_w1   = (const float*)d_in[5];
    const float* mlp_b1   = (const float*)d_in[6];
    const float* mlp_w2   = (const float*)d_in[7];
    const float* mlp_b2   = (const float*)d_in[8];
    const void*  batch    = d_in[9];
    const int*   edge_idx = (const int*)d_in[10];
    const int*   edge_typ = (const int*)d_in[11];
    float*       out      = (float*)d_out;

    k_main<<<GRID, BLK>>>(rel, layer_w, layer_b, ln_g, ln_b,
                          mlp_w1, mlp_b1, mlp_w2, mlp_b2,
                          batch, edge_idx, edge_typ, out);
}

// round 13
// speedup vs baseline: 1.4893x; 1.4893x over previous
#include <cuda_runtime.h>

#define BB 2
#define KK 33
#define NN 50000
#define EE 800000
#define RR 200
#define DD 64
#define LL 3
#define NROWS (BB*NN)          /* 100000 */
#define NWORDS (NROWS/32)      /* 3125, exact */
#define TABW (NN*2/32)         /* 3125 (== NWORDS) */
#define GRID 148
#define BLK 768
#define NTHREADS (GRID*BLK)    /* 113664 */
#define NWARPS (NTHREADS/32)   /* 3552 */
#define WPB ((NWORDS + GRID - 1)/GRID)   /* 22 mask words per block */
#define SC_ITERS 2             /* ceil((EE/4)/NTHREADS) */
#define ROWF 0x100000          /* worklist delta flag (row < 2^17) */

__device__ __align__(16) float g_x[NROWS*DD];     // NOT cleaned: rows are only
                                                  // read when xmask says written
__device__ __align__(16) float g_agg[NROWS*DD];   // invariant: zero at phase entry
__device__ unsigned g_xmask[NWORDS];
__device__ unsigned g_amask[NWORDS];              // invariant: zero at phase entry
__device__ unsigned g_tab[TABW];                  // 2 bits/node, mirrors xmask
__device__ float g_query[BB*DD];
__device__ int   g_h0[BB];
__device__ float g_zv[LL][DD];
__device__ int   g_zfl[LL];
__device__ int   g_b64;

// Tree grid barrier: per-block arrival slots + single release word.
// Generations are ABSOLUTE and monotone across launches/replays.
__device__ unsigned g_arrive[GRID];
__device__ volatile unsigned g_rel;

__device__ __forceinline__ void gridbar(unsigned target) {
    __syncthreads();
    if (blockIdx.x == 0) {
        int t = threadIdx.x;
        if (t > 0 && t < GRID) {
            volatile unsigned* a = (volatile unsigned*)&g_arrive[t];
            while (*a < target) __nanosleep(32);
        }
        __syncthreads();
        if (t == 0) { __threadfence(); g_rel = target; }
    } else {
        if (threadIdx.x == 0) {
            __threadfence();   // publish block's writes
            ((volatile unsigned*)g_arrive)[blockIdx.x] = target;
            while (g_rel < target) __nanosleep(32);
        }
    }
    __syncthreads();
}

__device__ __forceinline__ int clampi(int v, int hi) {
    return v < 0 ? 0 : (v >= hi ? hi - 1 : v);
}
// bit-interleave: bit i of x -> bit 2i
__device__ __forceinline__ unsigned ileave16(unsigned x) {
    x = (x | (x << 8)) & 0x00FF00FFu;
    x = (x | (x << 4)) & 0x0F0F0F0Fu;
    x = (x | (x << 2)) & 0x33333333u;
    x = (x | (x << 1)) & 0x55555555u;
    return x;
}

__global__ void __launch_bounds__(BLK, 1)
k_main(const float* __restrict__ rel,
       const float* __restrict__ layer_w,
       const float* __restrict__ layer_b,
       const float* __restrict__ ln_g,
       const float* __restrict__ ln_b,
       const float* __restrict__ w1,
       const float* __restrict__ b1,
       const float* __restrict__ w2,
       const float* __restrict__ b2,
       const void*  __restrict__ batch,
       const int*   __restrict__ edge_index,
       const int*   __restrict__ etype,
       float*       __restrict__ out)
{
    __shared__ float s_W[2*DD*DD];    // 32KB: current layer's weights
    __shared__ int   s_wl[WPB*32];    // block-local row worklist (<=704)
    __shared__ int   s_cnt;
    __shared__ float s_sb[LL][DD];
    __shared__ float s_mv[LL][2];
    __shared__ float s_feat[2*DD];
    __shared__ float s_hs[DD];
    __shared__ unsigned s_base;

    const int tid   = threadIdx.x;
    const int gid   = blockIdx.x * BLK + tid;
    const int lane  = tid & 31;
    const int bwarp = tid >> 5;                       // warp in block (0..23)

    if (tid == 0) s_base = g_rel;     // barrier generation base for this launch
    __syncthreads();

    // ---------------- P0: mask re-zero (+h0 seed) + setup ------------------
    // Every warp computes is64/h0/r0 from cached loads; each mask word is
    // written by exactly one thread (zero merged with the seed bits), so
    // there is no zero-vs-seed race. g_x is NOT cleaned: stale rows are
    // never read because xmask gates every read and delta rows skip loads.
    {
        const int* bw = (const int*)batch;
        const long long* bl64 = (const long long*)batch;
        int bad = 0;
        for (int i = lane; i < 99; i += 32)           // odd words 1..197
            if (bw[2*i + 1] != 0) bad = 1;
        int is64 = (__ballot_sync(0xffffffffu, bad) == 0);
        if (gid == 0) g_b64 = is64;
        int h0v[BB], r0v[BB];
        #pragma unroll
        for (int b = 0; b < BB; b++) {
            int i0 = (b*KK)*3;
            h0v[b] = clampi(is64 ? (int)bl64[i0    ] : bw[i0    ], NN);
            r0v[b] = clampi(is64 ? (int)bl64[i0 + 2] : bw[i0 + 2], RR);
        }
        for (int w = gid; w < NWORDS; w += NTHREADS) {   // NWORDS == TABW
            unsigned sx = 0, st = 0;
            #pragma unroll
            for (int b = 0; b < BB; b++) {
                int row = b*NN + h0v[b];
                if ((row >> 5) == w)    sx |= 1u << (row & 31);
                if ((h0v[b] >> 4) == w) st |= 1u << (((h0v[b] & 15) << 1) + b);
            }
            g_xmask[w] = sx;
            g_tab[w]   = st;
        }
        // block 0: boundary rows, query, h0 scalars
        if (blockIdx.x == 0 && bwarp < BB) {
            int b = bwarp;
            int row = b*NN + h0v[b];
            float2 q = ((const float2*)rel)[((size_t)b*RR + r0v[b])*32 + lane];
            ((float2*)g_x)[(size_t)row*32 + lane] = q;
            ((float2*)g_query)[b*32 + lane] = q;
            if (lane == 0) g_h0[b] = h0v[b];
        }
    }
    // z_l = relu(LN(layer_b[l])) — block 0
    if (blockIdx.x == 0 && tid < LL) g_zfl[tid] = 0;
    if (blockIdx.x == 0 && tid < LL*DD)
        s_sb[tid >> 6][tid & 63] = layer_b[tid];
    __syncthreads();
    if (blockIdx.x == 0 && tid < LL) {
        float su = 0.f, sq = 0.f;
        for (int i = 0; i < DD; i++) { float v = s_sb[tid][i]; su += v; sq += v*v; }
        float mu = su * (1.f/DD);
        s_mv[tid][0] = mu;
        s_mv[tid][1] = sq * (1.f/DD) - mu*mu;
    }
    __syncthreads();
    if (blockIdx.x == 0 && tid < LL*DD) {
        int l = tid >> 6, d = tid & 63;
        float v = s_sb[l][d];
        float z = (v - s_mv[l][0]) * rsqrtf(s_mv[l][1] + 1e-5f) * ln_g[tid] + ln_b[tid];
        z = fmaxf(z, 0.f);
        g_zv[l][d] = z;
        if (z != 0.f) atomicOr(&g_zfl[l], 1);
    }
    gridbar(s_base + 1);

    // ---------------- layers ----------------------------------------------
    for (int l = 0; l < LL; l++) {
        // stage this layer's weights into smem (overlaps with scatter)
        {
            const float4* Wsrc = (const float4*)(layer_w + (size_t)l*2*DD*DD);
            float4* Wdst = (float4*)s_W;
            for (int i = tid; i < 2*DD*DD/4; i += BLK) Wdst[i] = Wsrc[i];
            if (tid == 0) s_cnt = 0;
        }
        // ---- scatter: agg[b,dst] += x[b,src] * rel[b,etype] --------------
        {
            int4 s4v[SC_ITERS];
            unsigned pk[SC_ITERS];
            #pragma unroll
            for (int it = 0; it < SC_ITERS; it++) {
                int idx = gid + it * NTHREADS;
                s4v[it] = (idx*4 < EE) ? ((const int4*)edge_index)[idx]
                                       : make_int4(0, 0, 0, 0);
            }
            #pragma unroll
            for (int it = 0; it < SC_ITERS; it++) {
                int idx = gid + it * NTHREADS;
                unsigned p = 0;
                if (idx*4 < EE) {
                    p  = ((g_tab[s4v[it].x >> 4] >> ((s4v[it].x & 15) << 1)) & 3u);
                    p |= ((g_tab[s4v[it].y >> 4] >> ((s4v[it].y & 15) << 1)) & 3u) << 2;
                    p |= ((g_tab[s4v[it].z >> 4] >> ((s4v[it].z & 15) << 1)) & 3u) << 4;
                    p |= ((g_tab[s4v[it].w >> 4] >> ((s4v[it].w & 15) << 1)) & 3u) << 6;
                }
                pk[it] = p;
            }
            #pragma unroll
            for (int it = 0; it < SC_ITERS; it++) {
                if (__ballot_sync(0xffffffffu, pk[it] != 0) == 0) continue;
                int idx  = gid + it * NTHREADS;
                // batched, coalesced dst/etype prefetch for the whole group
                int4 d4 = ((const int4*)(edge_index + EE))[idx];
                int4 t4 = ((const int4*)etype)[idx];
                int srcs[4] = {s4v[it].x, s4v[it].y, s4v[it].z, s4v[it].w};
                int dsts[4] = {d4.x, d4.y, d4.z, d4.w};
                int typs[4] = {t4.x, t4.y, t4.z, t4.w};
                #pragma unroll
                for (int k = 0; k < 4; k++) {
                    unsigned prk = (pk[it] >> (2*k)) & 3u;
                    unsigned b0 = __ballot_sync(0xffffffffu, prk & 1u);
                    unsigned b1 = __ballot_sync(0xffffffffu, prk & 2u);
                    unsigned act = b0 | b1;
                    while (act) {
                        int j = __ffs(act) - 1;
                        act &= act - 1;
                        int sj = __shfl_sync(0xffffffffu, srcs[k], j);
                        int dj = __shfl_sync(0xffffffffu, dsts[k], j);
                        int tj = __shfl_sync(0xffffffffu, typs[k], j);
                        #pragma unroll
                        for (int b = 0; b < BB; b++) {
                            unsigned bb = b ? b1 : b0;
                            if (!((bb >> j) & 1)) continue;   // uniform
                            float2 xv = ((const float2*)g_x)[((size_t)(b*NN + sj))*32 + lane];
                            float2 rv = ((const float2*)rel)[((size_t)(b*RR + tj))*32 + lane];
                            float* ap = &g_agg[((size_t)(b*NN + dj))*DD + 2*lane];
                            atomicAdd(ap,     xv.x * rv.x);
                            atomicAdd(ap + 1, xv.y * rv.y);
                            if (lane == 0) {
                                int row = b*NN + dj;
                                atomicOr(&g_amask[row >> 5], 1u << (row & 31));
                            }
                        }
                    }
                }
            }
        }
        gridbar(s_base + 2 + 2*l);

        // ---- fused compact + update over this block's 22 mask words ------
        // Worklist entries carry a delta flag (bit 20): row newly activated
        // this layer => logical x row is all-zero (never loaded).
        if (tid < WPB) {
            int w = blockIdx.x * WPB + tid;
            if (w < NWORDS) {
                unsigned xm = g_xmask[w];
                unsigned am = g_amask[w];
                unsigned act = xm | am;
                unsigned delta = am & ~xm;
                if (am) {
                    g_amask[w] = 0u;
                    if (delta) {
                        g_xmask[w] = act;
                        if (l < LL - 1) {             // tab feeds next scatter only
                            #pragma unroll
                            for (int h = 0; h < 2; h++) {       // 16-row halves
                                unsigned bits = (delta >> (16*h)) & 0xFFFFu;
                                if (!bits) continue;
                                int rowbase = w * 32 + 16*h;    // multiple of 16
                                if (rowbase < NN)
                                    atomicOr(&g_tab[rowbase >> 4], ileave16(bits));
                                else {
                                    int node = rowbase - NN;    // NN%16==0
                                    atomicOr(&g_tab[node >> 4], ileave16(bits) << 1);
                                }
                            }
                        }
                    }
                }
                if (act) {
                    int n = __popc(act);
                    int base = atomicAdd(&s_cnt, n);
                    unsigned mm = act;
                    while (mm) {
                        int j = __ffs(mm) - 1; mm &= mm - 1;
                        s_wl[base++] = (w * 32 + j) | (((delta >> j) & 1u) ? ROWF : 0);
                    }
                }
            }
        }
        __syncthreads();

        // ---- update: one row per warp (R11 structure) + delta skip -------
        {
            int cnt = s_cnt;
            float bj0  = layer_b[l*DD + 2*lane], bj1  = layer_b[l*DD + 2*lane + 1];
            float gj0  = ln_g[l*DD + 2*lane],    gj1  = ln_g[l*DD + 2*lane + 1];
            float btj0 = ln_b[l*DD + 2*lane],    btj1 = ln_b[l*DD + 2*lane + 1];
            for (int i = bwarp; i < cnt; i += BLK/32) {
                int e   = s_wl[i];                 // warp-uniform broadcast
                int row = e & (ROWF - 1);
                int isd = (e & ROWF) ? 1 : 0;      // warp-uniform
                int b   = row / NN;
                int n   = row - b * NN;
                float2 a2 = ((float2*)g_agg)[(size_t)row*32 + lane];
                float2 x2 = make_float2(0.f, 0.f);
                if (!isd) x2 = ((float2*)g_x)[(size_t)row*32 + lane];
                if (n == g_h0[b]) {
                    a2.x += g_query[b*DD + 2*lane];
                    a2.y += g_query[b*DD + 2*lane + 1];
                }
                float acc0 = bj0, acc1 = bj1;
                #pragma unroll 8
                for (int ii = 0; ii < 32; ii++) {       // cat[0:64] = agg
                    float cx = __shfl_sync(0xffffffffu, a2.x, ii);
                    float cy = __shfl_sync(0xffffffffu, a2.y, ii);
                    float2 w0 = ((const float2*)(s_W + (2*ii    )*DD))[lane];
                    float2 w1v = ((const float2*)(s_W + (2*ii + 1)*DD))[lane];
                    acc0 += cx*w0.x + cy*w1v.x;
                    acc1 += cx*w0.y + cy*w1v.y;
                }
                if (!isd) {
                    #pragma unroll 8
                    for (int ii = 0; ii < 32; ii++) {   // cat[64:128] = x
                        float cx = __shfl_sync(0xffffffffu, x2.x, ii);
                        float cy = __shfl_sync(0xffffffffu, x2.y, ii);
                        float2 w0 = ((const float2*)(s_W + (64 + 2*ii    )*DD))[lane];
                        float2 w1v = ((const float2*)(s_W + (64 + 2*ii + 1)*DD))[lane];
                        acc0 += cx*w0.x + cy*w1v.x;
                        acc1 += cx*w0.y + cy*w1v.y;
                    }
                }
                float su = acc0 + acc1;
                float sq = acc0*acc0 + acc1*acc1;
                #pragma unroll
                for (int o = 16; o; o >>= 1) {
                    su += __shfl_xor_sync(0xffffffffu, su, o);
                    sq += __shfl_xor_sync(0xffffffffu, sq, o);
                }
                float mu  = su * (1.f/DD);
                float var = sq * (1.f/DD) - mu*mu;
                float rs  = rsqrtf(var + 1e-5f);
                float u0 = fmaxf((acc0 - mu)*rs*gj0 + btj0, 0.f);
                float u1 = fmaxf((acc1 - mu)*rs*gj1 + btj1, 0.f);
                x2.x += u0; x2.y += u1;
                ((float2*)g_x)[(size_t)row*32 + lane] = x2;
                ((float2*)g_agg)[(size_t)row*32 + lane] = make_float2(0.f, 0.f);
            }
            // cold path: dense z_l densify (z_l == 0 for these inputs).
            // Inactive rows hold logical x == 0, so ASSIGN (not +=) — their
            // g_x content may be stale under the no-clean policy.
            if (l < LL - 1 && g_zfl[l]) {
                for (int r = gid; r < NROWS; r += NTHREADS) {
                    if (!((g_xmask[r >> 5] >> (r & 31)) & 1)) {
                        for (int d = 0; d < DD; d++)
                            g_x[(size_t)r*DD + d] = g_zv[l][d];
                        atomicOr(&g_xmask[r >> 5], 1u << (r & 31));
                    }
                }
                for (int r = gid; r < TABW; r += NTHREADS)
                    g_tab[r] = 0xFFFFFFFFu;
            }
        }
        gridbar(s_base + 3 + 2*l);
    }

    // ---------------- score ------------------------------------------------
    if (blockIdx.x < BB*KK) {
        int b = blockIdx.x / KK, k = blockIdx.x % KK;
        if (tid < DD) {
            int ti = (b*KK + k)*3 + 1;
            int t  = clampi(g_b64 ? (int)((const long long*)batch)[ti]
                                  : ((const int*)batch)[ti], NN);
            int row = b*NN + t;
            float f;
            if ((g_xmask[row >> 5] >> (row & 31)) & 1)
                f = g_x[(size_t)row*DD + tid];
            else
                f = g_zfl[LL-1] ? g_zv[LL-1][tid] : 0.f;  // logical x == 0
            s_feat[tid]      = f;
            s_feat[DD + tid] = g_query[b*DD + tid];
        }
        __syncthreads();
        if (tid < DD) {
            float acc = b1[tid];
            #pragma unroll 8
            for (int i = 0; i < 2*DD; i++) acc += s_feat[i] * w1[i*DD + tid];
            float h = fmaxf(acc, 0.f);
            s_hs[tid] = h * w2[tid];
        }
        __syncthreads();
        if (tid == 0) {
            float s = b2[0];
            for (int i = 0; i < DD; i++) s += s_hs[i];
            out[b*KK + k] = s;
        }
    }
}

// ---------------------------------------------------------------------------
extern "C" void kernel_launch(void* const* d_in, const int* in_sizes, int n_in,
                              void* d_out, int out_size) {
    const float* rel      = (const float*)d_in[0];
    const float* layer_w  = (const float*)d_in[1];
    const float* layer_b  = (const float*)d_in[2];
    const float* ln_g     = (const float*)d_in[3];
    const float* ln_b     = (const float*)d_in[4];
    const float* mlp_w1   = (const float*)d_in[5];
    const float* mlp_b1   = (const float*)d_in[6];
    const float* mlp_w2   = (const float*)d_in[7];
    const float* mlp_b2   = (const float*)d_in[8];
    const void*  batch    = d_in[9];
    const int*   edge_idx = (const int*)d_in[10];
    const int*   edge_typ = (const int*)d_in[11];
    float*       out      = (float*)d_out;

    k_main<<<GRID, BLK>>>(rel, layer_w, layer_b, ln_g, ln_b,
                          mlp_w1, mlp_b1, mlp_w2, mlp_b2,
                          batch, edge_idx, edge_typ, out);
}

// round 14
// speedup vs baseline: 1.6915x; 1.1358x over previous
#include <cuda_runtime.h>

#define BB 2
#define KK 33
#define NN 50000
#define EE 800000
#define RR 200
#define DD 64
#define LL 3
#define NROWS (BB*NN)          /* 100000 */
#define NWORDS (NROWS/32)      /* 3125, exact */
#define TABW (NN*2/32)         /* 3125 (== NWORDS) */
#define GRID 148
#define BLK 768
#define NTHREADS (GRID*BLK)    /* 113664 */
#define NWARPS (NTHREADS/32)   /* 3552 */
#define WPB ((NWORDS + GRID - 1)/GRID)   /* 22 mask words per block */
#define SC_ITERS 2             /* ceil((EE/4)/NTHREADS) */
#define ROWF 0x100000          /* worklist delta flag (row < 2^17) */

__device__ __align__(16) float g_x[NROWS*DD];     // NOT cleaned: rows are only
                                                  // read when xmask says written
__device__ __align__(16) float g_agg[NROWS*DD];   // invariant: zero at phase entry
__device__ unsigned g_xmask[NWORDS];
__device__ unsigned g_amask[NWORDS];              // invariant: zero at phase entry
__device__ unsigned g_tab[TABW];                  // 2 bits/node, mirrors xmask
__device__ float g_query[BB*DD];
__device__ int   g_h0[BB];
__device__ float g_zv[LL][DD];
__device__ int   g_zfl[LL];
__device__ int   g_b64;

// Tree grid barrier: per-block arrival slots + single release word.
// Generations are ABSOLUTE and monotone across launches/replays.
__device__ unsigned g_arrive[GRID];
__device__ volatile unsigned g_rel;

__device__ __forceinline__ void gridbar(unsigned target) {
    __syncthreads();
    if (blockIdx.x == 0) {
        int t = threadIdx.x;
        if (t > 0 && t < GRID) {
            volatile unsigned* a = (volatile unsigned*)&g_arrive[t];
            while (*a < target) __nanosleep(32);
        }
        __syncthreads();
        if (t == 0) { __threadfence(); g_rel = target; }
    } else {
        if (threadIdx.x == 0) {
            __threadfence();   // publish block's writes
            ((volatile unsigned*)g_arrive)[blockIdx.x] = target;
            while (g_rel < target) __nanosleep(32);
        }
    }
    __syncthreads();
}

__device__ __forceinline__ int clampi(int v, int hi) {
    return v < 0 ? 0 : (v >= hi ? hi - 1 : v);
}
// bit-interleave: bit i of x -> bit 2i
__device__ __forceinline__ unsigned ileave16(unsigned x) {
    x = (x | (x << 8)) & 0x00FF00FFu;
    x = (x | (x << 4)) & 0x0F0F0F0Fu;
    x = (x | (x << 2)) & 0x33333333u;
    x = (x | (x << 1)) & 0x55555555u;
    return x;
}

__global__ void __launch_bounds__(BLK, 1)
k_main(const float* __restrict__ rel,
       const float* __restrict__ layer_w,
       const float* __restrict__ layer_b,
       const float* __restrict__ ln_g,
       const float* __restrict__ ln_b,
       const float* __restrict__ w1,
       const float* __restrict__ b1,
       const float* __restrict__ w2,
       const float* __restrict__ b2,
       const void*  __restrict__ batch,
       const int*   __restrict__ edge_index,
       const int*   __restrict__ etype,
       float*       __restrict__ out)
{
    __shared__ float    s_W[2*DD*DD];    // 32KB: current layer's weights
    __shared__ unsigned s_tab[TABW];     // 12.5KB: activity table (layers 1,2)
    __shared__ int      s_wl[WPB*32];    // block-local row worklist (<=704)
    __shared__ int      s_cnt;
    __shared__ float    s_sb[LL][DD];
    __shared__ float    s_mv[LL][2];
    __shared__ unsigned s_base;

    const int tid   = threadIdx.x;
    const int gid   = blockIdx.x * BLK + tid;
    const int lane  = tid & 31;
    const int bwarp = tid >> 5;                       // warp in block (0..23)

    if (tid == 0) s_base = g_rel;     // barrier generation base for this launch
    __syncthreads();

    // ---------------- P0: dtype detect + mask re-zero(+seed) + setup -------
    // No grid barrier after this phase: layer-0 scatter consumes only
    // registers (h0v / q). All P0 global writes are first consumed after the
    // post-scatter-0 barrier.
    int h0v[BB], r0v[BB];
    {
        const int* bw = (const int*)batch;
        const long long* bl64 = (const long long*)batch;
        int bad = 0;
        for (int i = lane; i < 99; i += 32)           // odd words 1..197
            if (bw[2*i + 1] != 0) bad = 1;
        int is64 = (__ballot_sync(0xffffffffu, bad) == 0);
        if (gid == 0) g_b64 = is64;
        #pragma unroll
        for (int b = 0; b < BB; b++) {
            int i0 = (b*KK)*3;
            h0v[b] = clampi(is64 ? (int)bl64[i0    ] : bw[i0    ], NN);
            r0v[b] = clampi(is64 ? (int)bl64[i0 + 2] : bw[i0 + 2], RR);
        }
        for (int w = gid; w < NWORDS; w += NTHREADS) {   // NWORDS == TABW
            unsigned sx = 0, st = 0;
            #pragma unroll
            for (int b = 0; b < BB; b++) {
                int row = b*NN + h0v[b];
                if ((row >> 5) == w)    sx |= 1u << (row & 31);
                if ((h0v[b] >> 4) == w) st |= 1u << (((h0v[b] & 15) << 1) + b);
            }
            g_xmask[w] = sx;
            g_tab[w]   = st;
        }
        // block 0: boundary rows, query, h0 scalars
        if (blockIdx.x == 0 && bwarp < BB) {
            int b = bwarp;
            int row = b*NN + h0v[b];
            float2 q = ((const float2*)rel)[((size_t)b*RR + r0v[b])*32 + lane];
            ((float2*)g_x)[(size_t)row*32 + lane] = q;
            ((float2*)g_query)[b*32 + lane] = q;
            if (lane == 0) g_h0[b] = h0v[b];
        }
    }
    // z_l = relu(LN(layer_b[l])) — block 0
    if (blockIdx.x == 0 && tid < LL) g_zfl[tid] = 0;
    if (blockIdx.x == 0 && tid < LL*DD)
        s_sb[tid >> 6][tid & 63] = layer_b[tid];
    __syncthreads();
    if (blockIdx.x == 0 && tid < LL) {
        float su = 0.f, sq = 0.f;
        for (int i = 0; i < DD; i++) { float v = s_sb[tid][i]; su += v; sq += v*v; }
        float mu = su * (1.f/DD);
        s_mv[tid][0] = mu;
        s_mv[tid][1] = sq * (1.f/DD) - mu*mu;
    }
    __syncthreads();
    if (blockIdx.x == 0 && tid < LL*DD) {
        int l = tid >> 6, d = tid & 63;
        float v = s_sb[l][d];
        float z = (v - s_mv[l][0]) * rsqrtf(s_mv[l][1] + 1e-5f) * ln_g[tid] + ln_b[tid];
        z = fmaxf(z, 0.f);
        g_zv[l][d] = z;
        if (z != 0.f) atomicOr(&g_zfl[l], 1);
    }

    // ---------------- layers ----------------------------------------------
    for (int l = 0; l < LL; l++) {
        // stage this layer's weights (+ activity table for l>=1) into smem
        {
            const float4* Wsrc = (const float4*)(layer_w + (size_t)l*2*DD*DD);
            float4* Wdst = (float4*)s_W;
            for (int i = tid; i < 2*DD*DD/4; i += BLK) Wdst[i] = Wsrc[i];
            if (l > 0)
                for (int i = tid; i < TABW; i += BLK) s_tab[i] = g_tab[i];
            if (tid == 0) s_cnt = 0;
        }
        __syncthreads();

        // ---- scatter: agg[b,dst] += x[b,src] * rel[b,etype] --------------
        {
            float2 qv0 = make_float2(0.f, 0.f), qv1 = make_float2(0.f, 0.f);
            if (l == 0) {   // layer-0 message value lives in registers
                qv0 = ((const float2*)rel)[((size_t)0*RR + r0v[0])*32 + lane];
                qv1 = ((const float2*)rel)[((size_t)1*RR + r0v[1])*32 + lane];
            }
            int4 s4v[SC_ITERS];
            unsigned pk[SC_ITERS];
            #pragma unroll
            for (int it = 0; it < SC_ITERS; it++) {
                int idx = gid + it * NTHREADS;
                s4v[it] = (idx*4 < EE) ? ((const int4*)edge_index)[idx]
                                       : make_int4(-1, -1, -1, -1);
            }
            #pragma unroll
            for (int it = 0; it < SC_ITERS; it++) {
                int idx = gid + it * NTHREADS;
                unsigned p = 0;
                if (idx*4 < EE) {
                    if (l == 0) {   // register probe: src == h0?
                        p  = (unsigned)((s4v[it].x == h0v[0]) | ((s4v[it].x == h0v[1]) << 1));
                        p |= (unsigned)((s4v[it].y == h0v[0]) | ((s4v[it].y == h0v[1]) << 1)) << 2;
                        p |= (unsigned)((s4v[it].z == h0v[0]) | ((s4v[it].z == h0v[1]) << 1)) << 4;
                        p |= (unsigned)((s4v[it].w == h0v[0]) | ((s4v[it].w == h0v[1]) << 1)) << 6;
                    } else {        // smem table probe
                        p  = ((s_tab[s4v[it].x >> 4] >> ((s4v[it].x & 15) << 1)) & 3u);
                        p |= ((s_tab[s4v[it].y >> 4] >> ((s4v[it].y & 15) << 1)) & 3u) << 2;
                        p |= ((s_tab[s4v[it].z >> 4] >> ((s4v[it].z & 15) << 1)) & 3u) << 4;
                        p |= ((s_tab[s4v[it].w >> 4] >> ((s4v[it].w & 15) << 1)) & 3u) << 6;
                    }
                }
                pk[it] = p;
            }
            #pragma unroll
            for (int it = 0; it < SC_ITERS; it++) {
                if (__ballot_sync(0xffffffffu, pk[it] != 0) == 0) continue;
                int idx  = gid + it * NTHREADS;
                // batched, coalesced dst/etype prefetch for the whole group
                int4 d4 = ((const int4*)(edge_index + EE))[idx];
                int4 t4 = ((const int4*)etype)[idx];
                int srcs[4] = {s4v[it].x, s4v[it].y, s4v[it].z, s4v[it].w};
                int dsts[4] = {d4.x, d4.y, d4.z, d4.w};
                int typs[4] = {t4.x, t4.y, t4.z, t4.w};
                #pragma unroll
                for (int k = 0; k < 4; k++) {
                    unsigned prk = (pk[it] >> (2*k)) & 3u;
                    unsigned b0 = __ballot_sync(0xffffffffu, prk & 1u);
                    unsigned b1 = __ballot_sync(0xffffffffu, prk & 2u);
                    unsigned act = b0 | b1;
                    while (act) {
                        int j = __ffs(act) - 1;
                        act &= act - 1;
                        int sj = __shfl_sync(0xffffffffu, srcs[k], j);
                        int dj = __shfl_sync(0xffffffffu, dsts[k], j);
                        int tj = __shfl_sync(0xffffffffu, typs[k], j);
                        #pragma unroll
                        for (int b = 0; b < BB; b++) {
                            unsigned bb = b ? b1 : b0;
                            if (!((bb >> j) & 1)) continue;   // uniform
                            float2 xv;
                            if (l == 0) xv = b ? qv1 : qv0;
                            else        xv = ((const float2*)g_x)[((size_t)(b*NN + sj))*32 + lane];
                            float2 rv = ((const float2*)rel)[((size_t)(b*RR + tj))*32 + lane];
                            float* ap = &g_agg[((size_t)(b*NN + dj))*DD + 2*lane];
                            atomicAdd(ap,     xv.x * rv.x);
                            atomicAdd(ap + 1, xv.y * rv.y);
                            if (lane == 0) {
                                int row = b*NN + dj;
                                atomicOr(&g_amask[row >> 5], 1u << (row & 31));
                            }
                        }
                    }
                }
            }
        }
        gridbar(s_base + 1 + 2*l);

        // ---- fused compact + update over this block's 22 mask words ------
        if (tid < WPB) {
            int w = blockIdx.x * WPB + tid;
            if (w < NWORDS) {
                unsigned xm = g_xmask[w];
                unsigned am = g_amask[w];
                unsigned act = xm | am;
                unsigned delta = am & ~xm;
                if (am) {
                    g_amask[w] = 0u;
                    if (delta) {
                        g_xmask[w] = act;
                        if (l < LL - 1) {             // tab feeds next scatter only
                            #pragma unroll
                            for (int h = 0; h < 2; h++) {       // 16-row halves
                                unsigned bits = (delta >> (16*h)) & 0xFFFFu;
                                if (!bits) continue;
                                int rowbase = w * 32 + 16*h;    // multiple of 16
                                if (rowbase < NN)
                                    atomicOr(&g_tab[rowbase >> 4], ileave16(bits));
                                else {
                                    int node = rowbase - NN;    // NN%16==0
                                    atomicOr(&g_tab[node >> 4], ileave16(bits) << 1);
                                }
                            }
                        }
                    }
                }
                if (act) {
                    int n = __popc(act);
                    int base = atomicAdd(&s_cnt, n);
                    unsigned mm = act;
                    while (mm) {
                        int j = __ffs(mm) - 1; mm &= mm - 1;
                        s_wl[base++] = (w * 32 + j) | (((delta >> j) & 1u) ? ROWF : 0);
                    }
                }
            }
        }
        __syncthreads();

        // ---- update: one row per warp + delta skip -----------------------
        {
            int cnt = s_cnt;
            float bj0  = layer_b[l*DD + 2*lane], bj1  = layer_b[l*DD + 2*lane + 1];
            float gj0  = ln_g[l*DD + 2*lane],    gj1  = ln_g[l*DD + 2*lane + 1];
            float btj0 = ln_b[l*DD + 2*lane],    btj1 = ln_b[l*DD + 2*lane + 1];
            for (int i = bwarp; i < cnt; i += BLK/32) {
                int e   = s_wl[i];                 // warp-uniform broadcast
                int row = e & (ROWF - 1);
                int isd = (e & ROWF) ? 1 : 0;      // warp-uniform
                int b   = row / NN;
                int n   = row - b * NN;
                float2 a2 = ((float2*)g_agg)[(size_t)row*32 + lane];
                float2 x2 = make_float2(0.f, 0.f);
                if (!isd) x2 = ((float2*)g_x)[(size_t)row*32 + lane];
                if (n == g_h0[b]) {
                    a2.x += g_query[b*DD + 2*lane];
                    a2.y += g_query[b*DD + 2*lane + 1];
                }
                float acc0 = bj0, acc1 = bj1;
                #pragma unroll 8
                for (int ii = 0; ii < 32; ii++) {       // cat[0:64] = agg
                    float cx = __shfl_sync(0xffffffffu, a2.x, ii);
                    float cy = __shfl_sync(0xffffffffu, a2.y, ii);
                    float2 w0 = ((const float2*)(s_W + (2*ii    )*DD))[lane];
                    float2 w1v = ((const float2*)(s_W + (2*ii + 1)*DD))[lane];
                    acc0 += cx*w0.x + cy*w1v.x;
                    acc1 += cx*w0.y + cy*w1v.y;
                }
                if (!isd) {
                    #pragma unroll 8
                    for (int ii = 0; ii < 32; ii++) {   // cat[64:128] = x
                        float cx = __shfl_sync(0xffffffffu, x2.x, ii);
                        float cy = __shfl_sync(0xffffffffu, x2.y, ii);
                        float2 w0 = ((const float2*)(s_W + (64 + 2*ii    )*DD))[lane];
                        float2 w1v = ((const float2*)(s_W + (64 + 2*ii + 1)*DD))[lane];
                        acc0 += cx*w0.x + cy*w1v.x;
                        acc1 += cx*w0.y + cy*w1v.y;
                    }
                }
                float su = acc0 + acc1;
                float sq = acc0*acc0 + acc1*acc1;
                #pragma unroll
                for (int o = 16; o; o >>= 1) {
                    su += __shfl_xor_sync(0xffffffffu, su, o);
                    sq += __shfl_xor_sync(0xffffffffu, sq, o);
                }
                float mu  = su * (1.f/DD);
                float var = sq * (1.f/DD) - mu*mu;
                float rs  = rsqrtf(var + 1e-5f);
                float u0 = fmaxf((acc0 - mu)*rs*gj0 + btj0, 0.f);
                float u1 = fmaxf((acc1 - mu)*rs*gj1 + btj1, 0.f);
                x2.x += u0; x2.y += u1;
                ((float2*)g_x)[(size_t)row*32 + lane] = x2;
                ((float2*)g_agg)[(size_t)row*32 + lane] = make_float2(0.f, 0.f);
            }
            // cold path: dense z_l densify (z_l == 0 for these inputs).
            if (l < LL - 1 && g_zfl[l]) {
                for (int r = gid; r < NROWS; r += NTHREADS) {
                    if (!((g_xmask[r >> 5] >> (r & 31)) & 1)) {
                        for (int d = 0; d < DD; d++)
                            g_x[(size_t)r*DD + d] = g_zv[l][d];   // logical 0 + z
                        atomicOr(&g_xmask[r >> 5], 1u << (r & 31));
                    }
                }
                for (int r = gid; r < TABW; r += NTHREADS)
                    g_tab[r] = 0xFFFFFFFFu;
            }
        }
        if (l < LL - 1) gridbar(s_base + 2 + 2*l);
    }

    // ---------------- score at owner block (no final grid barrier) ---------
    // Rows are updated only by their mask-word owner block, so after this
    // block's own update (+__syncthreads) any (b,k) tail row in its word
    // range is final. Each of the 66 pairs has exactly one owner.
    __syncthreads();
    for (int bk = bwarp; bk < BB*KK; bk += BLK/32) {
        int b = bk / KK, k = bk % KK;
        int ti = (b*KK + k)*3 + 1;
        int t  = clampi(g_b64 ? (int)((const long long*)batch)[ti]
                              : ((const int*)batch)[ti], NN);
        int row = b*NN + t;
        if ((row >> 5) / WPB != blockIdx.x) continue;     // warp-uniform
        float2 xf;
        if ((g_xmask[row >> 5] >> (row & 31)) & 1)
            xf = ((float2*)g_x)[(size_t)row*32 + lane];
        else if (g_zfl[LL-1])
            xf = make_float2(g_zv[LL-1][2*lane], g_zv[LL-1][2*lane+1]);
        else
            xf = make_float2(0.f, 0.f);
        float2 qf = ((float2*)g_query)[b*32 + lane];
        float acc0 = b1[2*lane], acc1 = b1[2*lane + 1];
        #pragma unroll 8
        for (int ii = 0; ii < 32; ii++) {                 // feat[0:64] = hidden
            float cx = __shfl_sync(0xffffffffu, xf.x, ii);
            float cy = __shfl_sync(0xffffffffu, xf.y, ii);
            float2 w0 = ((const float2*)(w1 + (2*ii    )*DD))[lane];
            float2 w1v = ((const float2*)(w1 + (2*ii + 1)*DD))[lane];
            acc0 += cx*w0.x + cy*w1v.x;
            acc1 += cx*w0.y + cy*w1v.y;
        }
        #pragma unroll 8
        for (int ii = 0; ii < 32; ii++) {                 // feat[64:128] = query
            float cx = __shfl_sync(0xffffffffu, qf.x, ii);
            float cy = __shfl_sync(0xffffffffu, qf.y, ii);
            float2 w0 = ((const float2*)(w1 + (64 + 2*ii    )*DD))[lane];
            float2 w1v = ((const float2*)(w1 + (64 + 2*ii + 1)*DD))[lane];
            acc0 += cx*w0.x + cy*w1v.x;
            acc1 += cx*w0.y + cy*w1v.y;
        }
        float h0 = fmaxf(acc0, 0.f), h1 = fmaxf(acc1, 0.f);
        float s = h0 * w2[2*lane] + h1 * w2[2*lane + 1];
        #pragma unroll
        for (int o = 16; o; o >>= 1)
            s += __shfl_xor_sync(0xffffffffu, s, o);
        if (lane == 0) out[bk] = s + b2[0];
    }
}

// ---------------------------------------------------------------------------
extern "C" void kernel_launch(void* const* d_in, const int* in_sizes, int n_in,
                              void* d_out, int out_size) {
    const float* rel      = (const float*)d_in[0];
    const float* layer_w  = (const float*)d_in[1];
    const float* layer_b  = (const float*)d_in[2];
    const float* ln_g     = (const float*)d_in[3];
    const float* ln_b     = (const float*)d_in[4];
    const float* mlp_w1   = (const float*)d_in[5];
    const float* mlp_b1   = (const float*)d_in[6];
    const float* mlp_w2   = (const float*)d_in[7];
    const float* mlp_b2   = (const float*)d_in[8];
    const void*  batch    = d_in[9];
    const int*   edge_idx = (const int*)d_in[10];
    const int*   edge_typ = (const int*)d_in[11];
    float*       out      = (float*)d_out;

    k_main<<<GRID, BLK>>>(rel, layer_w, layer_b, ln_g, ln_b,
                          mlp_w1, mlp_b1, mlp_w2, mlp_b2,
                          batch, edge_idx, edge_typ, out);
}